// round 16
// baseline (speedup 1.0000x reference)
#include <cuda_runtime.h>
#include <cuda_bf16.h>
#include <cstdint>

// ---------------- Problem constants ----------------
#define NB      64
#define NPG     180
#define NN      (NB*NPG)    // 11520
#define NE      (NN*16)     // 184320
#define NH      4
#define FC      256
#define HF      1024
#define LAT     256
#define BOT     128
#define KIN     (LAT+BOT)
#define NEG_SLOPE 0.2f
#define MAXE    96          // per-dst edge cap (Poisson(16): max deg ~38)
#define KC      32          // K chunks of 32 (K = 1024 for all mma GEMMs)
#define HCAT    768         // merged head width (3 x 256)
#define K2ROW   512         // u32 (bf16x2) words per row of length-1024 K

// ---------------- Scratch ----------------
__device__ float    g_xin[NB*KIN];
__device__ float    g_zc [NB*LAT];
__device__ float    g_Y  [NB*HF];
__device__ float    g_h  [(size_t)NN*HF];
__device__ float    g_t  [(size_t)NN*HCAT];
__device__ float    g_as [NN*NH];
__device__ float    g_ad [NN*NH];
__device__ uint32_t g_xhi[(size_t)NN*K2ROW];   // A operand, bf16 hi pairs
__device__ uint32_t g_xlo[(size_t)NN*K2ROW];   // A operand, bf16 lo pairs
__device__ uint32_t g_Bhi[(size_t)HF*K2ROW];   // B operand packed [n][k2], bf16 hi
__device__ uint32_t g_Blo[(size_t)HF*K2ROW];   // bf16 lo
__device__ float    g_bcat[HCAT];
__device__ int      g_cnt[NN];
__device__ int      g_rowptr[NN+1];
__device__ int      g_wp [NN];
__device__ int      g_col[NE];

// ---------------- helpers ----------------
__device__ __forceinline__ void cpa16(uint32_t dst, const void* src) {
    asm volatile("cp.async.cg.shared.global [%0], [%1], 16;" :: "r"(dst), "l"(src));
}
__device__ __forceinline__ uint32_t pack_bf16(__nv_bfloat16 lo16, __nv_bfloat16 hi16) {
    return ((uint32_t)__bfloat16_as_ushort(hi16) << 16) | __bfloat16_as_ushort(lo16);
}
__device__ __forceinline__ void split2(float v0, float v1, uint32_t& hi, uint32_t& lo) {
    __nv_bfloat16 h0 = __float2bfloat16(v0);
    __nv_bfloat16 h1 = __float2bfloat16(v1);
    __nv_bfloat16 l0 = __float2bfloat16(v0 - __bfloat162float(h0));
    __nv_bfloat16 l1 = __float2bfloat16(v1 - __bfloat162float(h1));
    hi = pack_bf16(h0, h1);
    lo = pack_bf16(l0, l1);
}
#define MMA_BF16(ac, a0, a1, a2, a3, b0, b1)                                   \
    asm volatile("mma.sync.aligned.m16n8k16.row.col.f32.bf16.bf16.f32 "        \
        "{%0,%1,%2,%3}, {%4,%5,%6,%7}, {%8,%9}, {%0,%1,%2,%3};"                \
        : "+f"((ac)[0]), "+f"((ac)[1]), "+f"((ac)[2]), "+f"((ac)[3])           \
        : "r"(a0), "r"(a1), "r"(a2), "r"(a3), "r"(b0), "r"(b1))

// ---------------- weight pre-split: W[1024,Nc] -> packed [n][k2] bf16 pairs ----
__global__ void wsplit_k(const float* __restrict__ W, uint32_t* __restrict__ hi,
                         uint32_t* __restrict__ lo, int Nc)
{
    int idx = blockIdx.x*blockDim.x + threadIdx.x;
    if (idx >= Nc*K2ROW) return;
    int n = idx >> 9, k2 = idx & 511;
    float v0 = W[(size_t)(2*k2  )*Nc + n];
    float v1 = W[(size_t)(2*k2+1)*Nc + n];
    split2(v0, v1, hi[idx], lo[idx]);
}

// concat Wp|Ws|Wt ([1024,256] each) -> packed [n][k2] over n=0..767; + bias concat
__global__ void hcat_k(const float* __restrict__ Wp, const float* __restrict__ Ws,
                       const float* __restrict__ Wt,
                       const float* __restrict__ bp, const float* __restrict__ bs,
                       const float* __restrict__ bt,
                       uint32_t* __restrict__ hi, uint32_t* __restrict__ lo,
                       float* __restrict__ bcat)
{
    int idx = blockIdx.x*blockDim.x + threadIdx.x;
    if (idx >= HCAT*K2ROW) return;
    int n = idx >> 9, k2 = idx & 511;
    const float* W = (n < 256) ? Wp : ((n < 512) ? Ws : Wt);
    int nn = n & 255;
    float v0 = W[(size_t)(2*k2  )*FC + nn];
    float v1 = W[(size_t)(2*k2+1)*FC + nn];
    split2(v0, v1, hi[idx], lo[idx]);
    if (idx < HCAT)
        bcat[idx] = (idx < 256) ? bp[idx] : ((idx < 512) ? bs[idx-256] : bt[idx-512]);
}

// ---------------- split-BF16 mma.sync GEMM ----------------
// C[M,Nc] = A[M,1024] @ B[1024,Nc] (+bias)(+relu).  M%128==0, Nc%128==0.
// A,B pre-split bf16 hi/lo, packed as u32 [row][k2].  acc += HH + HL + LH.
// CTA 128x128, BK=32, 256 thr = 8 warps (4M x 2N), warp tile 32x64. 2-stage.
#define PU   20               // smem pitch (u32): frag bank = (20g+tig)%32, conflict-free
#define ABUF 2560             // 128 rows x PU
#define STGU (4*ABUF)         // AH AL BH BL = 10240 u32 = 40KB/stage
#define SMEM_MG (2*STGU*4)    // 81920 B (2 CTA/SM)

__global__ void __launch_bounds__(256, 2) mgemm_k(
    const uint32_t* __restrict__ Ahi, const uint32_t* __restrict__ Alo,
    const uint32_t* __restrict__ Bhi, const uint32_t* __restrict__ Blo,
    float* __restrict__ C, int Nc, const float* __restrict__ bias, int doRelu)
{
    extern __shared__ uint32_t smu[];
    const int tid  = threadIdx.x;
    const int wid  = tid >> 5, lane = tid & 31;
    const int wm   = wid >> 1, wn   = wid & 1;
    const int g    = lane >> 2, tig = lane & 3;
    const int m0   = blockIdx.y * 128;
    const int n0   = blockIdx.x * 128;

    float acc[2][8][4];
    #pragma unroll
    for (int mt = 0; mt < 2; mt++)
        #pragma unroll
        for (int nt = 0; nt < 8; nt++)
            #pragma unroll
            for (int i = 0; i < 4; i++) acc[mt][nt][i] = 0.f;

    auto loadst = [&](int c, int s) {
        uint32_t* AH = smu + s*STGU;
        uint32_t* AL = AH + ABUF;
        uint32_t* BH = AH + 2*ABUF;
        uint32_t* BL = AH + 3*ABUF;
        const int kb = c << 4;                      // 16 u32 per chunk
        #pragma unroll
        for (int j = 0; j < 2; j++) {
            int idx = tid + j*256;                  // 0..511: 128 rows x 4 quads
            int row = idx >> 2, q = (idx & 3) << 2;
            uint32_t so = row*PU + q;
            size_t ga = (size_t)(m0 + row)*K2ROW + kb + q;
            cpa16((uint32_t)__cvta_generic_to_shared(AH + so), Ahi + ga);
            cpa16((uint32_t)__cvta_generic_to_shared(AL + so), Alo + ga);
            size_t gb = (size_t)(n0 + row)*K2ROW + kb + q;
            cpa16((uint32_t)__cvta_generic_to_shared(BH + so), Bhi + gb);
            cpa16((uint32_t)__cvta_generic_to_shared(BL + so), Blo + gb);
        }
        asm volatile("cp.async.commit_group;" ::: "memory");
    };

    auto compute = [&](int s) {
        const uint32_t* AH = smu + s*STGU;
        const uint32_t* AL = AH + ABUF;
        const uint32_t* BH = AH + 2*ABUF;
        const uint32_t* BL = AH + 3*ABUF;
        const int ar = (wm*32 + g)*PU + tig;
        const int br = (wn*64 + g)*PU + tig;
        #pragma unroll
        for (int ks = 0; ks < 2; ks++) {
            uint32_t ah[2][4], al[2][4];
            #pragma unroll
            for (int mt = 0; mt < 2; mt++) {
                int b = ar + mt*16*PU + ks*8;
                ah[mt][0] = AH[b];          ah[mt][1] = AH[b + 8*PU];
                ah[mt][2] = AH[b + 4];      ah[mt][3] = AH[b + 8*PU + 4];
                al[mt][0] = AL[b];          al[mt][1] = AL[b + 8*PU];
                al[mt][2] = AL[b + 4];      al[mt][3] = AL[b + 8*PU + 4];
            }
            #pragma unroll
            for (int ntg = 0; ntg < 2; ntg++) {
                uint32_t bh[4][2], bl[4][2];
                #pragma unroll
                for (int q = 0; q < 4; q++) {
                    int off = br + (ntg*4 + q)*8*PU + ks*8;
                    bh[q][0] = BH[off];  bh[q][1] = BH[off + 4];
                    bl[q][0] = BL[off];  bl[q][1] = BL[off + 4];
                }
                #pragma unroll
                for (int mt = 0; mt < 2; mt++)
                    #pragma unroll
                    for (int q = 0; q < 4; q++) {
                        float* ac = acc[mt][ntg*4 + q];
                        MMA_BF16(ac, ah[mt][0], ah[mt][1], ah[mt][2], ah[mt][3], bh[q][0], bh[q][1]);
                        MMA_BF16(ac, ah[mt][0], ah[mt][1], ah[mt][2], ah[mt][3], bl[q][0], bl[q][1]);
                        MMA_BF16(ac, al[mt][0], al[mt][1], al[mt][2], al[mt][3], bh[q][0], bh[q][1]);
                    }
            }
        }
    };

    loadst(0, 0);
    loadst(1, 1);
    for (int c = 0; c < KC; c++) {
        int s = c & 1;
        if (c < KC - 2) asm volatile("cp.async.wait_group 1;" ::: "memory");
        else            asm volatile("cp.async.wait_group 0;" ::: "memory");
        __syncthreads();
        compute(s);
        __syncthreads();
        if (c + 2 < KC) loadst(c + 2, s);
    }

    // epilogue (same acc mapping as m16n8k8 path)
    #pragma unroll
    for (int mt = 0; mt < 2; mt++) {
        int r = m0 + wm*32 + mt*16 + g;
        #pragma unroll
        for (int nt = 0; nt < 8; nt++) {
            int col = n0 + wn*64 + nt*8 + 2*tig;
            float2 v0 = make_float2(acc[mt][nt][0], acc[mt][nt][1]);
            float2 v1 = make_float2(acc[mt][nt][2], acc[mt][nt][3]);
            if (bias) {
                float2 bv = *(const float2*)(bias + col);
                v0.x += bv.x; v0.y += bv.y;
                v1.x += bv.x; v1.y += bv.y;
            }
            if (doRelu) {
                v0.x = fmaxf(v0.x, 0.f); v0.y = fmaxf(v0.y, 0.f);
                v1.x = fmaxf(v1.x, 0.f); v1.y = fmaxf(v1.y, 0.f);
            }
            *(float2*)(C + (size_t)r*Nc + col)       = v0;
            *(float2*)(C + (size_t)(r + 8)*Nc + col) = v1;
        }
    }
}

// ---------------- small utility kernels ----------------
__global__ void concat_k(const float* __restrict__ z, const float* __restrict__ c,
                         float* __restrict__ out)
{
    int idx = blockIdx.x*blockDim.x + threadIdx.x;
    if (idx >= NB*KIN) return;
    int b = idx / KIN, i = idx % KIN;
    out[idx] = (i < LAT) ? z[b*LAT + i] : c[b*BOT + (i-LAT)];
}

__global__ void build_h1_k(const float* __restrict__ Y, const float* __restrict__ W1,
                           float* __restrict__ h)
{
    int idx = blockIdx.x*blockDim.x + threadIdx.x;
    if (idx >= NN*(HF/4)) return;
    int n  = idx >> 8;
    int c4 = (idx & 255) << 2;
    int b = n / NPG, o = n % NPG;
    float4 yv = *(const float4*)(Y + (size_t)b*HF + c4);
    float4 wv = *(const float4*)(W1 + (size_t)(LAT + o)*HF + c4);
    yv.x += wv.x; yv.y += wv.y; yv.z += wv.z; yv.w += wv.w;
    *(float4*)(h + (size_t)n*HF + c4) = yv;
}

__global__ void zero_cnt_k(int* __restrict__ cnt)
{
    int i = blockIdx.x*blockDim.x + threadIdx.x;
    if (i < NN) cnt[i] = 0;
}

__global__ void count_k(const int* __restrict__ dst, int* __restrict__ cnt)
{
    int e = blockIdx.x*blockDim.x + threadIdx.x;
    if (e < NE) atomicAdd(&cnt[dst[e]], 1);
}

__global__ void scan_k(const int* __restrict__ cnt, int* __restrict__ rowptr,
                       int* __restrict__ wp)
{
    __shared__ int sums[256];
    const int CH = (NN + 255) / 256;
    int t = threadIdx.x;
    int base = t * CH;
    int s = 0;
    for (int i = 0; i < CH; i++) { int idx = base + i; if (idx < NN) s += cnt[idx]; }
    sums[t] = s;
    __syncthreads();
    if (t == 0) {
        int run = 0;
        for (int i = 0; i < 256; i++) { int v = sums[i]; sums[i] = run; run += v; }
        rowptr[NN] = run;
    }
    __syncthreads();
    int run = sums[t];
    for (int i = 0; i < CH; i++) {
        int idx = base + i;
        if (idx < NN) { rowptr[idx] = run; wp[idx] = run; run += cnt[idx]; }
    }
}

__global__ void scatter_k(const int* __restrict__ src, const int* __restrict__ dst,
                          int* __restrict__ wp, int* __restrict__ col)
{
    int e = blockIdx.x*blockDim.x + threadIdx.x;
    if (e >= NE) return;
    int d = dst[e];
    int p = atomicAdd(&wp[d], 1);
    col[p] = src[e];
}

// ---------------- attention coefficients ----------------
__global__ void att_k(const float* __restrict__ h,
                      const float* __restrict__ att_s, const float* __restrict__ att_d,
                      float* __restrict__ as_, float* __restrict__ ad_)
{
    int gw   = (blockIdx.x*blockDim.x + threadIdx.x) >> 5;
    int lane = threadIdx.x & 31;
    if (gw >= NN*NH) return;
    int n = gw >> 2, hh = gw & 3;
    const float* hp = h + (size_t)n*HF + hh*FC;
    const float* sp = att_s + hh*FC;
    const float* dp = att_d + hh*FC;
    float s = 0.f, d = 0.f;
    #pragma unroll 4
    for (int c = lane; c < FC; c += 32) {
        float v = hp[c];
        s += v * sp[c];
        d += v * dp[c];
    }
    #pragma unroll
    for (int o = 16; o; o >>= 1) {
        s += __shfl_down_sync(0xffffffffu, s, o);
        d += __shfl_down_sync(0xffffffffu, d, o);
    }
    if (lane == 0) { as_[n*NH+hh] = s; ad_[n*NH+hh] = d; }
}

// ---------------- per-dst softmax + aggregation (+bias+relu) -> split bf16 x ----
__global__ void agg_k(const float* __restrict__ h,
                      const float* __restrict__ as_, const float* __restrict__ ad_,
                      const int* __restrict__ rowptr, const int* __restrict__ col,
                      const float* __restrict__ bias,
                      uint32_t* __restrict__ xhi, uint32_t* __restrict__ xlo)
{
    __shared__ int   src_s[MAXE];
    __shared__ float e_s[MAXE*NH];
    __shared__ float stat[12];
    __shared__ float ad_sh[4];

    int d   = blockIdx.x;
    int tid = threadIdx.x;
    int r0  = rowptr[d];
    int deg = rowptr[d+1] - r0;
    if (deg > MAXE) deg = MAXE;

    if (tid < 4) ad_sh[tid] = ad_[d*NH + tid];
    __syncthreads();

    for (int j = tid; j < deg; j += 256) {
        int s = col[r0 + j];
        src_s[j] = s;
        #pragma unroll
        for (int hh = 0; hh < NH; hh++) {
            float e = as_[s*NH + hh] + ad_sh[hh];
            e = (e > 0.f) ? e : NEG_SLOPE * e;
            e_s[j*NH + hh] = e;
        }
    }
    __syncthreads();

    if (tid < 4) {
        int hh = tid;
        float eself = as_[d*NH + hh] + ad_sh[hh];
        eself = (eself > 0.f) ? eself : NEG_SLOPE * eself;
        float m = eself;
        for (int j = 0; j < deg; j++) m = fmaxf(m, e_s[j*NH + hh]);
        float s = __expf(eself - m);
        for (int j = 0; j < deg; j++) s += __expf(e_s[j*NH + hh] - m);
        float inv = 1.f / (s + 1e-16f);
        stat[hh]     = m;
        stat[4 + hh] = inv;
        stat[8 + hh] = __expf(eself - m) * inv;
    }
    __syncthreads();

    for (int j = tid; j < deg; j += 256) {
        #pragma unroll
        for (int hh = 0; hh < NH; hh++)
            e_s[j*NH + hh] = __expf(e_s[j*NH + hh] - stat[hh]) * stat[4 + hh];
    }
    __syncthreads();

    int c4 = tid * 4;
    int hh = c4 >> 8;
    float4 acc;
    {
        float4 v = *(const float4*)(h + (size_t)d*HF + c4);
        float a = stat[8 + hh];
        acc.x = a*v.x; acc.y = a*v.y; acc.z = a*v.z; acc.w = a*v.w;
    }
    #pragma unroll 4
    for (int j = 0; j < deg; j++) {
        float a = e_s[j*NH + hh];
        float4 v = *(const float4*)(h + (size_t)src_s[j]*HF + c4);
        acc.x += a*v.x; acc.y += a*v.y; acc.z += a*v.z; acc.w += a*v.w;
    }
    float4 bv = *(const float4*)(bias + c4);
    acc.x = fmaxf(acc.x + bv.x, 0.f);
    acc.y = fmaxf(acc.y + bv.y, 0.f);
    acc.z = fmaxf(acc.z + bv.z, 0.f);
    acc.w = fmaxf(acc.w + bv.w, 0.f);

    uint32_t h01, l01, h23, l23;
    split2(acc.x, acc.y, h01, l01);
    split2(acc.z, acc.w, h23, l23);
    size_t base = (size_t)d*K2ROW + tid*2;
    xhi[base] = h01; xhi[base + 1] = h23;
    xlo[base] = l01; xlo[base + 1] = l23;
}

// ---------------- small fp32 tiled GEMM (M=64 preamble only) ----------------
__global__ void sgemm_k(const float* __restrict__ A, const float* __restrict__ B,
                        const float* __restrict__ bias, float* __restrict__ C,
                        int M, int Nc, int K, int doRelu)
{
    __shared__ float As[8][128];
    __shared__ float Bs[8][128];
    const int tid = threadIdx.x;
    const int bx = blockIdx.x, by = blockIdx.y;

    const int a_row = tid >> 1;
    const int a_k   = (tid & 1) << 2;
    const int b_k   = tid >> 5;
    const int b_col = (tid & 31) << 2;

    const int ty = tid >> 4;
    const int tx = tid & 15;
    const int row0 = by*128 + ty*8;
    const int col0 = bx*128 + tx*8;

    float acc[8][8];
    #pragma unroll
    for (int i = 0; i < 8; i++)
        #pragma unroll
        for (int j = 0; j < 8; j++) acc[i][j] = 0.f;

    const int arow_g = by*128 + a_row;
    for (int k0 = 0; k0 < K; k0 += 8) {
        float4 av = make_float4(0.f,0.f,0.f,0.f);
        if (arow_g < M)
            av = *(const float4*)(A + (size_t)arow_g*K + k0 + a_k);
        As[a_k+0][a_row] = av.x;
        As[a_k+1][a_row] = av.y;
        As[a_k+2][a_row] = av.z;
        As[a_k+3][a_row] = av.w;
        float4 bv = *(const float4*)(B + (size_t)(k0 + b_k)*Nc + bx*128 + b_col);
        *(float4*)&Bs[b_k][b_col] = bv;
        __syncthreads();

        #pragma unroll
        for (int k = 0; k < 8; k++) {
            float ar[8], br[8];
            *(float4*)&ar[0] = *(const float4*)&As[k][ty*8];
            *(float4*)&ar[4] = *(const float4*)&As[k][ty*8+4];
            *(float4*)&br[0] = *(const float4*)&Bs[k][tx*8];
            *(float4*)&br[4] = *(const float4*)&Bs[k][tx*8+4];
            #pragma unroll
            for (int i = 0; i < 8; i++)
                #pragma unroll
                for (int j = 0; j < 8; j++)
                    acc[i][j] += ar[i] * br[j];
        }
        __syncthreads();
    }

    #pragma unroll
    for (int i = 0; i < 8; i++) {
        int r = row0 + i;
        if (r >= M) break;
        #pragma unroll
        for (int j = 0; j < 8; j += 4) {
            float4 v = make_float4(acc[i][j], acc[i][j+1], acc[i][j+2], acc[i][j+3]);
            if (bias) {
                v.x += bias[col0+j+0]; v.y += bias[col0+j+1];
                v.z += bias[col0+j+2]; v.w += bias[col0+j+3];
            }
            if (doRelu) {
                v.x = fmaxf(v.x, 0.f); v.y = fmaxf(v.y, 0.f);
                v.z = fmaxf(v.z, 0.f); v.w = fmaxf(v.w, 0.f);
            }
            *(float4*)(C + (size_t)r*Nc + col0 + j) = v;
        }
    }
}

// ---------------- tiny head projection (t row stride HCAT) ----------------
__global__ void head2_k(const float* __restrict__ t, const float* __restrict__ Wf,
                        const float* __restrict__ bf, float* __restrict__ out, int od)
{
    int warp = (blockIdx.x*blockDim.x + threadIdx.x) >> 5;
    int lane = threadIdx.x & 31;
    if (warp >= NN) return;
    const float* tp = t + (size_t)warp*HCAT;
    float a0 = 0.f, a1 = 0.f;
    #pragma unroll 4
    for (int c = lane; c < FC; c += 32) {
        float v = tp[c];
        a0 += v * Wf[c*od + 0];
        if (od > 1) a1 += v * Wf[c*od + 1];
    }
    #pragma unroll
    for (int o = 16; o; o >>= 1) {
        a0 += __shfl_down_sync(0xffffffffu, a0, o);
        a1 += __shfl_down_sync(0xffffffffu, a1, o);
    }
    if (lane == 0) {
        out[(size_t)warp*od + 0] = a0 + bf[0];
        if (od > 1) out[(size_t)warp*od + 1] = a1 + bf[1];
    }
}

// ---------------- launch ----------------
extern "C" void kernel_launch(void* const* d_in, const int* in_sizes, int n_in,
                              void* d_out, int out_size)
{
    const float* z      = (const float*)d_in[0];
    const float* cond   = (const float*)d_in[1];
    const int*   ei     = (const int*)  d_in[2];
    const float* W_init = (const float*)d_in[4];
    const float* b_init = (const float*)d_in[5];
    const float* W1  = (const float*)d_in[6];
    const float* as1 = (const float*)d_in[7];
    const float* ad1 = (const float*)d_in[8];
    const float* b1  = (const float*)d_in[9];
    const float* W2  = (const float*)d_in[10];
    const float* as2 = (const float*)d_in[11];
    const float* ad2 = (const float*)d_in[12];
    const float* b2  = (const float*)d_in[13];
    const float* W3  = (const float*)d_in[14];
    const float* as3 = (const float*)d_in[15];
    const float* ad3 = (const float*)d_in[16];
    const float* b3  = (const float*)d_in[17];
    const float* Wp  = (const float*)d_in[18];
    const float* bp  = (const float*)d_in[19];
    const float* Wfp = (const float*)d_in[20];
    const float* bfp = (const float*)d_in[21];
    const float* Ws  = (const float*)d_in[22];
    const float* bs  = (const float*)d_in[23];
    const float* Wfs = (const float*)d_in[24];
    const float* bfs = (const float*)d_in[25];
    const float* Wt  = (const float*)d_in[26];
    const float* bt  = (const float*)d_in[27];
    const float* Wft = (const float*)d_in[28];
    const float* bft = (const float*)d_in[29];
    float* out = (float*)d_out;

    const int* esrc = ei;
    const int* edst = ei + NE;

    float *pxin, *pzc, *pY, *ph, *pas, *pad, *pt, *pbc;
    uint32_t *pxhi, *pxlo, *phiB, *ploB;
    int *pcnt, *prow, *pwp, *pcol;
    cudaGetSymbolAddress((void**)&pxin, g_xin);
    cudaGetSymbolAddress((void**)&pzc,  g_zc);
    cudaGetSymbolAddress((void**)&pY,   g_Y);
    cudaGetSymbolAddress((void**)&ph,   g_h);
    cudaGetSymbolAddress((void**)&pas,  g_as);
    cudaGetSymbolAddress((void**)&pad,  g_ad);
    cudaGetSymbolAddress((void**)&pt,   g_t);
    cudaGetSymbolAddress((void**)&pxhi, g_xhi);
    cudaGetSymbolAddress((void**)&pxlo, g_xlo);
    cudaGetSymbolAddress((void**)&phiB, g_Bhi);
    cudaGetSymbolAddress((void**)&ploB, g_Blo);
    cudaGetSymbolAddress((void**)&pbc,  g_bcat);
    cudaGetSymbolAddress((void**)&pcnt, g_cnt);
    cudaGetSymbolAddress((void**)&prow, g_rowptr);
    cudaGetSymbolAddress((void**)&pwp,  g_wp);
    cudaGetSymbolAddress((void**)&pcol, g_col);

    cudaFuncSetAttribute(mgemm_k, cudaFuncAttributeMaxDynamicSharedMemorySize, SMEM_MG);

    // 1) input projection (small, SIMT fp32)
    concat_k<<<(NB*KIN + 255)/256, 256>>>(z, cond, pxin);
    {
        dim3 g(LAT/128, 1);
        sgemm_k<<<g, 256>>>(pxin, W_init, b_init, pzc, NB, LAT, KIN, 1);
    }
    {
        dim3 g(HF/128, 1);
        sgemm_k<<<g, 256>>>(pzc, W1, nullptr, pY, NB, HF, LAT, 0);
    }
    // 2) CSR by destination
    zero_cnt_k<<<(NN + 255)/256, 256>>>(pcnt);
    count_k<<<(NE + 255)/256, 256>>>(edst, pcnt);
    scan_k<<<1, 256>>>(pcnt, prow, pwp);
    scatter_k<<<(NE + 255)/256, 256>>>(esrc, edst, pwp, pcol);

    // 3) h1 = Y[batch] + W1[256+order]
    build_h1_k<<<(NN*(HF/4) + 255)/256, 256>>>(pY, W1, ph);

    // 4) layer 1
    att_k<<<(NN*NH*32 + 255)/256, 256>>>(ph, as1, ad1, pas, pad);
    agg_k<<<NN, 256>>>(ph, pas, pad, prow, pcol, b1, pxhi, pxlo);

    // 5) layer 2
    wsplit_k<<<(HF*K2ROW + 255)/256, 256>>>(W2, phiB, ploB, HF);
    mgemm_k<<<dim3(HF/128, NN/128), 256, SMEM_MG>>>(pxhi, pxlo, phiB, ploB, ph, HF, nullptr, 0);
    att_k<<<(NN*NH*32 + 255)/256, 256>>>(ph, as2, ad2, pas, pad);
    agg_k<<<NN, 256>>>(ph, pas, pad, prow, pcol, b2, pxhi, pxlo);

    // 6) layer 3
    wsplit_k<<<(HF*K2ROW + 255)/256, 256>>>(W3, phiB, ploB, HF);
    mgemm_k<<<dim3(HF/128, NN/128), 256, SMEM_MG>>>(pxhi, pxlo, phiB, ploB, ph, HF, nullptr, 0);
    att_k<<<(NN*NH*32 + 255)/256, 256>>>(ph, as3, ad3, pas, pad);
    agg_k<<<NN, 256>>>(ph, pas, pad, prow, pcol, b3, pxhi, pxlo);

    // 7) heads: merged t = relu(x @ [Wp|Ws|Wt] + bcat) in ONE Nc=768 GEMM
    hcat_k<<<(HCAT*K2ROW + 255)/256, 256>>>(Wp, Ws, Wt, bp, bs, bt, phiB, ploB, pbc);
    mgemm_k<<<dim3(HCAT/128, NN/128), 256, SMEM_MG>>>(pxhi, pxlo, phiB, ploB, pt, HCAT, pbc, 1);

    head2_k<<<(NN*32 + 255)/256, 256>>>(pt,       Wfp, bfp, out, 2);
    head2_k<<<(NN*32 + 255)/256, 256>>>(pt + 256, Wfs, bfs, out + (size_t)2*NN, 2);
    head2_k<<<(NN*32 + 255)/256, 256>>>(pt + 512, Wft, bft, out + (size_t)4*NN, 1);
}

// round 17
// speedup vs baseline: 1.1176x; 1.1176x over previous
#include <cuda_runtime.h>
#include <cstdint>

// ---------------- Problem constants ----------------
#define NB      64
#define NPG     180
#define NN      (NB*NPG)    // 11520
#define NE      (NN*16)     // 184320
#define NH      4
#define FC      256
#define HF      1024
#define LAT     256
#define BOT     128
#define KIN     (LAT+BOT)
#define NEG_SLOPE 0.2f
#define MAXE    96          // per-dst edge cap (Poisson(16): max deg ~38)
#define KC      32          // K chunks of 32 (K = 1024 for all mma GEMMs)
#define HCAT    768         // merged head width (3 x 256)

// ---------------- Scratch ----------------
__device__ float g_xin[NB*KIN];
__device__ float g_zc [NB*LAT];
__device__ float g_Y  [NB*HF];
__device__ float g_h  [(size_t)NN*HF];
__device__ float g_x  [(size_t)NN*HF];
__device__ float g_as [NN*NH];
__device__ float g_ad [NN*NH];
__device__ float g_YS [NB*NH];
__device__ float g_YD [NB*NH];
__device__ float g_WS [NPG*NH];
__device__ float g_WD [NPG*NH];
__device__ float g_t  [(size_t)NN*HCAT];
__device__ float g_Bhi[(size_t)HF*HF];     // pre-split weight (tf32 hi), 4MB
__device__ float g_Blo[(size_t)HF*HF];     // residual lo, 4MB
__device__ float g_bcat[HCAT];
__device__ int   g_cnt[NN];
__device__ int   g_rowptr[NN+1];
__device__ int   g_wp [NN];
__device__ int   g_col[NE];

// ---------------- helpers ----------------
__device__ __forceinline__ void cpa16(uint32_t dst, const float* src) {
    asm volatile("cp.async.cg.shared.global [%0], [%1], 16;" :: "r"(dst), "l"(src));
}
__device__ __forceinline__ uint32_t tf32_hi(float x) {
    uint32_t r;
    asm("cvt.rna.tf32.f32 %0, %1;" : "=r"(r) : "f"(x));
    return r;
}
#define MMA_TF32(ac, a0, a1, a2, a3, b0, b1)                                   \
    asm volatile("mma.sync.aligned.m16n8k8.row.col.f32.tf32.tf32.f32 "         \
        "{%0,%1,%2,%3}, {%4,%5,%6,%7}, {%8,%9}, {%0,%1,%2,%3};"                \
        : "+f"((ac)[0]), "+f"((ac)[1]), "+f"((ac)[2]), "+f"((ac)[3])           \
        : "r"(a0), "r"(a1), "r"(a2), "r"(a3), "r"(b0), "r"(b1))

// ---------------- weight pre-split kernels (R10) ----------------
__global__ void wsplit_k(const float* __restrict__ W, float* __restrict__ hi,
                         float* __restrict__ lo, int n)
{
    int idx = blockIdx.x*blockDim.x + threadIdx.x;
    if (idx >= n) return;
    float v = W[idx];
    float h = __uint_as_float(tf32_hi(v));
    hi[idx] = h;
    lo[idx] = v - h;
}

__global__ void hcat_k(const float* __restrict__ Wp, const float* __restrict__ Ws,
                       const float* __restrict__ Wt,
                       const float* __restrict__ bp, const float* __restrict__ bs,
                       const float* __restrict__ bt,
                       float* __restrict__ hi, float* __restrict__ lo,
                       float* __restrict__ bcat)
{
    int idx = blockIdx.x*blockDim.x + threadIdx.x;
    if (idx >= HF*HCAT) return;
    int k = idx / HCAT, c = idx % HCAT;
    const float* W = (c < 256) ? Wp : ((c < 512) ? Ws : Wt);
    int cc = c & 255;
    float v = W[(size_t)k*FC + cc];
    float h = __uint_as_float(tf32_hi(v));
    hi[idx] = h;
    lo[idx] = v - h;
    if (idx < HCAT)
        bcat[idx] = (idx < 256) ? bp[idx] : ((idx < 512) ? bs[idx-256] : bt[idx-512]);
}

// ---------------- 3xTF32 mma.sync GEMM (R10, frozen inner loop) ----------------
// + optional fused attention-coefficient reduction in the epilogue:
//   a_s[r][hh0] += sum_col C[r][col]*avs[col] (hh0 = n0>>8; one head per CTA tile)
#define PA 36
#define PB 136               // b-frag bank = 8*tig+g, conflict-free
#define ASTG (128*PA)
#define BSTG (32*PB)
#define STG  (ASTG + 2*BSTG)
#define SMEM_MG (2*STG*4)    // 106496 B

__global__ void __launch_bounds__(256, 2) mgemm_k(
    const float* __restrict__ A, const float* __restrict__ Bhi,
    const float* __restrict__ Blo, float* __restrict__ C,
    int Nc, const float* __restrict__ bias, int doRelu,
    const float* __restrict__ avs, const float* __restrict__ avd,
    float* __restrict__ asOut, float* __restrict__ adOut)
{
    extern __shared__ float sm[];
    const int tid  = threadIdx.x;
    const int wid  = tid >> 5, lane = tid & 31;
    const int wm   = wid >> 1, wn   = wid & 1;
    const int g    = lane >> 2, tig = lane & 3;
    const int m0   = blockIdx.y * 128;
    const int n0   = blockIdx.x * 128;

    float acc[2][8][4];
    #pragma unroll
    for (int mt = 0; mt < 2; mt++)
        #pragma unroll
        for (int nt = 0; nt < 8; nt++)
            #pragma unroll
            for (int i = 0; i < 4; i++) acc[mt][nt][i] = 0.f;

    auto loadst = [&](int c, int s) {
        float* Asm = sm + s*STG;
        float* Bh  = Asm + ASTG;
        float* Bl  = Bh + BSTG;
        const int k0 = c << 5;
        #pragma unroll
        for (int j = 0; j < 4; j++) {
            int idx = tid + j*256;
            int row = idx >> 3, cf = (idx & 7) << 2;
            uint32_t dst = (uint32_t)__cvta_generic_to_shared(Asm + row*PA + cf);
            cpa16(dst, A + (size_t)(m0 + row)*HF + k0 + cf);
        }
        #pragma unroll
        for (int j = 0; j < 4; j++) {
            int idx = tid + j*256;
            int row = idx >> 5, cf = (idx & 31) << 2;
            size_t goff = (size_t)(k0 + row)*Nc + n0 + cf;
            uint32_t d1 = (uint32_t)__cvta_generic_to_shared(Bh + row*PB + cf);
            cpa16(d1, Bhi + goff);
            uint32_t d2 = (uint32_t)__cvta_generic_to_shared(Bl + row*PB + cf);
            cpa16(d2, Blo + goff);
        }
        asm volatile("cp.async.commit_group;" ::: "memory");
    };

    auto compute = [&](int s) {
        const float* Asm = sm + s*STG;
        const float* Bh  = Asm + ASTG;
        const float* Bl  = Bh + BSTG;
        const float* ab  = Asm + (wm*32 + g)*PA + tig;
        const int    bo  = tig*PB + wn*64 + g;
        #pragma unroll
        for (int ks = 0; ks < 4; ks++) {
            uint32_t ah[2][4], al[2][4];
            #pragma unroll
            for (int mt = 0; mt < 2; mt++) {
                const float* p = ab + mt*16*PA + ks*8;
                float f0 = p[0], f1 = p[8*PA], f2 = p[4], f3 = p[8*PA + 4];
                ah[mt][0] = tf32_hi(f0); al[mt][0] = __float_as_uint(f0 - __uint_as_float(ah[mt][0]));
                ah[mt][1] = tf32_hi(f1); al[mt][1] = __float_as_uint(f1 - __uint_as_float(ah[mt][1]));
                ah[mt][2] = tf32_hi(f2); al[mt][2] = __float_as_uint(f2 - __uint_as_float(ah[mt][2]));
                ah[mt][3] = tf32_hi(f3); al[mt][3] = __float_as_uint(f3 - __uint_as_float(ah[mt][3]));
            }
            #pragma unroll
            for (int ntg = 0; ntg < 2; ntg++) {
                uint32_t bh[4][2], bl[4][2];
                #pragma unroll
                for (int q = 0; q < 4; q++) {
                    int off = bo + ks*8*PB + (ntg*4 + q)*8;
                    bh[q][0] = __float_as_uint(Bh[off]);
                    bh[q][1] = __float_as_uint(Bh[off + 4*PB]);
                    bl[q][0] = __float_as_uint(Bl[off]);
                    bl[q][1] = __float_as_uint(Bl[off + 4*PB]);
                }
                #pragma unroll
                for (int mt = 0; mt < 2; mt++)
                    #pragma unroll
                    for (int q = 0; q < 4; q++) {
                        float* ac = acc[mt][ntg*4 + q];
                        MMA_TF32(ac, ah[mt][0], ah[mt][1], ah[mt][2], ah[mt][3], bh[q][0], bh[q][1]);
                        MMA_TF32(ac, ah[mt][0], ah[mt][1], ah[mt][2], ah[mt][3], bl[q][0], bl[q][1]);
                        MMA_TF32(ac, al[mt][0], al[mt][1], al[mt][2], al[mt][3], bh[q][0], bh[q][1]);
                    }
            }
        }
    };

    loadst(0, 0);
    loadst(1, 1);
    for (int c = 0; c < KC; c++) {
        int s = c & 1;
        if (c < KC - 2) asm volatile("cp.async.wait_group 1;" ::: "memory");
        else            asm volatile("cp.async.wait_group 0;" ::: "memory");
        __syncthreads();
        compute(s);
        __syncthreads();
        if (c + 2 < KC) loadst(c + 2, s);
    }

    // epilogue (+ optional fused att reduction)
    const int hh0 = n0 >> 8;
    #pragma unroll
    for (int mt = 0; mt < 2; mt++) {
        int r = m0 + wm*32 + mt*16 + g;
        float s0 = 0.f, d0 = 0.f, s1 = 0.f, d1 = 0.f;
        #pragma unroll
        for (int nt = 0; nt < 8; nt++) {
            int col = n0 + wn*64 + nt*8 + 2*tig;
            float2 v0 = make_float2(acc[mt][nt][0], acc[mt][nt][1]);
            float2 v1 = make_float2(acc[mt][nt][2], acc[mt][nt][3]);
            if (bias) {
                float2 bv = *(const float2*)(bias + col);
                v0.x += bv.x; v0.y += bv.y;
                v1.x += bv.x; v1.y += bv.y;
            }
            if (doRelu) {
                v0.x = fmaxf(v0.x, 0.f); v0.y = fmaxf(v0.y, 0.f);
                v1.x = fmaxf(v1.x, 0.f); v1.y = fmaxf(v1.y, 0.f);
            }
            if (avs) {
                float2 cs = *(const float2*)(avs + col);
                float2 cd = *(const float2*)(avd + col);
                s0 += v0.x*cs.x + v0.y*cs.y;
                d0 += v0.x*cd.x + v0.y*cd.y;
                s1 += v1.x*cs.x + v1.y*cs.y;
                d1 += v1.x*cd.x + v1.y*cd.y;
            }
            *(float2*)(C + (size_t)r*Nc + col)       = v0;
            *(float2*)(C + (size_t)(r + 8)*Nc + col) = v1;
        }
        if (avs) {
            atomicAdd(&asOut[r*4 + hh0],     s0);
            atomicAdd(&adOut[r*4 + hh0],     d0);
            atomicAdd(&asOut[(r+8)*4 + hh0], s1);
            atomicAdd(&adOut[(r+8)*4 + hh0], d1);
        }
    }
}

// ---------------- small utility kernels ----------------
__global__ void concat_k(const float* __restrict__ z, const float* __restrict__ c,
                         float* __restrict__ out)
{
    int idx = blockIdx.x*blockDim.x + threadIdx.x;
    if (idx >= NB*KIN) return;
    int b = idx / KIN, i = idx % KIN;
    out[idx] = (i < LAT) ? z[b*LAT + i] : c[b*BOT + (i-LAT)];
}

__global__ void build_h1_k(const float* __restrict__ Y, const float* __restrict__ W1,
                           float* __restrict__ h)
{
    int idx = blockIdx.x*blockDim.x + threadIdx.x;
    if (idx >= NN*(HF/4)) return;
    int n  = idx >> 8;
    int c4 = (idx & 255) << 2;
    int b = n / NPG, o = n % NPG;
    float4 yv = *(const float4*)(Y + (size_t)b*HF + c4);
    float4 wv = *(const float4*)(W1 + (size_t)(LAT + o)*HF + c4);
    yv.x += wv.x; yv.y += wv.y; yv.z += wv.z; yv.w += wv.w;
    *(float4*)(h + (size_t)n*HF + c4) = yv;
}

__global__ void zero_cnt_k(int* __restrict__ cnt)
{
    int i = blockIdx.x*blockDim.x + threadIdx.x;
    if (i < NN) cnt[i] = 0;
}

__global__ void zero2_k(float* __restrict__ a, float* __restrict__ b)
{
    int i = blockIdx.x*blockDim.x + threadIdx.x;
    if (i < NN*NH) { a[i] = 0.f; b[i] = 0.f; }
}

__global__ void count_k(const int* __restrict__ dst, int* __restrict__ cnt)
{
    int e = blockIdx.x*blockDim.x + threadIdx.x;
    if (e < NE) atomicAdd(&cnt[dst[e]], 1);
}

__global__ void scan_k(const int* __restrict__ cnt, int* __restrict__ rowptr,
                       int* __restrict__ wp)
{
    __shared__ int sums[256];
    const int CH = (NN + 255) / 256;
    int t = threadIdx.x;
    int base = t * CH;
    int s = 0;
    for (int i = 0; i < CH; i++) { int idx = base + i; if (idx < NN) s += cnt[idx]; }
    sums[t] = s;
    __syncthreads();
    if (t == 0) {
        int run = 0;
        for (int i = 0; i < 256; i++) { int v = sums[i]; sums[i] = run; run += v; }
        rowptr[NN] = run;
    }
    __syncthreads();
    int run = sums[t];
    for (int i = 0; i < CH; i++) {
        int idx = base + i;
        if (idx < NN) { rowptr[idx] = run; wp[idx] = run; run += cnt[idx]; }
    }
}

__global__ void scatter_k(const int* __restrict__ src, const int* __restrict__ dst,
                          int* __restrict__ wp, int* __restrict__ col)
{
    int e = blockIdx.x*blockDim.x + threadIdx.x;
    if (e >= NE) return;
    int d = dst[e];
    int p = atomicAdd(&wp[d], 1);
    col[p] = src[e];
}

// ---------------- generic per-row attention dots (layer-1 decomposition) ------
// outS[r*4+hh] = dot(M[r] slice hh, avs[hh]);  outD likewise.
__global__ void dotrow_k(const float* __restrict__ M,
                         const float* __restrict__ avs, const float* __restrict__ avd,
                         float* __restrict__ outS, float* __restrict__ outD, int rows)
{
    int gw   = (blockIdx.x*blockDim.x + threadIdx.x) >> 5;
    int lane = threadIdx.x & 31;
    if (gw >= rows*NH) return;
    int r = gw >> 2, hh = gw & 3;
    const float* mp = M + (size_t)r*HF + hh*FC;
    const float* sp = avs + hh*FC;
    const float* dp = avd + hh*FC;
    float s = 0.f, d = 0.f;
    #pragma unroll 4
    for (int c = lane; c < FC; c += 32) {
        float v = mp[c];
        s += v * sp[c];
        d += v * dp[c];
    }
    #pragma unroll
    for (int o = 16; o; o >>= 1) {
        s += __shfl_down_sync(0xffffffffu, s, o);
        d += __shfl_down_sync(0xffffffffu, d, o);
    }
    if (lane == 0) { outS[r*4 + hh] = s; outD[r*4 + hh] = d; }
}

// as1[n][h] = YS[b][h] + WS[o][h]  (h1 = Y[b] + W1[256+o], dot is linear)
__global__ void attcomb_k(const float* __restrict__ YS, const float* __restrict__ YD,
                          const float* __restrict__ WS, const float* __restrict__ WD,
                          float* __restrict__ as_, float* __restrict__ ad_)
{
    int idx = blockIdx.x*blockDim.x + threadIdx.x;
    if (idx >= NN*NH) return;
    int n = idx >> 2, hh = idx & 3;
    int b = n / NPG, o = n % NPG;
    as_[idx] = YS[b*4 + hh] + WS[o*4 + hh];
    ad_[idx] = YD[b*4 + hh] + WD[o*4 + hh];
}

// ---------------- per-dst softmax + aggregation (+bias+relu) ----------------
__global__ void agg_k(const float* __restrict__ h,
                      const float* __restrict__ as_, const float* __restrict__ ad_,
                      const int* __restrict__ rowptr, const int* __restrict__ col,
                      const float* __restrict__ bias, float* __restrict__ xout)
{
    __shared__ int   src_s[MAXE];
    __shared__ float e_s[MAXE*NH];
    __shared__ float stat[12];
    __shared__ float ad_sh[4];

    int d   = blockIdx.x;
    int tid = threadIdx.x;
    int r0  = rowptr[d];
    int deg = rowptr[d+1] - r0;
    if (deg > MAXE) deg = MAXE;

    if (tid < 4) ad_sh[tid] = ad_[d*NH + tid];
    __syncthreads();

    for (int j = tid; j < deg; j += 256) {
        int s = col[r0 + j];
        src_s[j] = s;
        #pragma unroll
        for (int hh = 0; hh < NH; hh++) {
            float e = as_[s*NH + hh] + ad_sh[hh];
            e = (e > 0.f) ? e : NEG_SLOPE * e;
            e_s[j*NH + hh] = e;
        }
    }
    __syncthreads();

    if (tid < 4) {
        int hh = tid;
        float eself = as_[d*NH + hh] + ad_sh[hh];
        eself = (eself > 0.f) ? eself : NEG_SLOPE * eself;
        float m = eself;
        for (int j = 0; j < deg; j++) m = fmaxf(m, e_s[j*NH + hh]);
        float s = __expf(eself - m);
        for (int j = 0; j < deg; j++) s += __expf(e_s[j*NH + hh] - m);
        float inv = 1.f / (s + 1e-16f);
        stat[hh]     = m;
        stat[4 + hh] = inv;
        stat[8 + hh] = __expf(eself - m) * inv;
    }
    __syncthreads();

    for (int j = tid; j < deg; j += 256) {
        #pragma unroll
        for (int hh = 0; hh < NH; hh++)
            e_s[j*NH + hh] = __expf(e_s[j*NH + hh] - stat[hh]) * stat[4 + hh];
    }
    __syncthreads();

    int c4 = tid * 4;
    int hh = c4 >> 8;
    float4 acc;
    {
        float4 v = *(const float4*)(h + (size_t)d*HF + c4);
        float a = stat[8 + hh];
        acc.x = a*v.x; acc.y = a*v.y; acc.z = a*v.z; acc.w = a*v.w;
    }
    #pragma unroll 4
    for (int j = 0; j < deg; j++) {
        float a = e_s[j*NH + hh];
        float4 v = *(const float4*)(h + (size_t)src_s[j]*HF + c4);
        acc.x += a*v.x; acc.y += a*v.y; acc.z += a*v.z; acc.w += a*v.w;
    }
    float4 bv = *(const float4*)(bias + c4);
    acc.x = fmaxf(acc.x + bv.x, 0.f);
    acc.y = fmaxf(acc.y + bv.y, 0.f);
    acc.z = fmaxf(acc.z + bv.z, 0.f);
    acc.w = fmaxf(acc.w + bv.w, 0.f);
    *(float4*)(xout + (size_t)d*HF + c4) = acc;
}

// ---------------- small fp32 tiled GEMM (M=64 preamble only) ----------------
__global__ void sgemm_k(const float* __restrict__ A, const float* __restrict__ B,
                        const float* __restrict__ bias, float* __restrict__ C,
                        int M, int Nc, int K, int doRelu)
{
    __shared__ float As[8][128];
    __shared__ float Bs[8][128];
    const int tid = threadIdx.x;
    const int bx = blockIdx.x, by = blockIdx.y;

    const int a_row = tid >> 1;
    const int a_k   = (tid & 1) << 2;
    const int b_k   = tid >> 5;
    const int b_col = (tid & 31) << 2;

    const int ty = tid >> 4;
    const int tx = tid & 15;
    const int row0 = by*128 + ty*8;
    const int col0 = bx*128 + tx*8;

    float acc[8][8];
    #pragma unroll
    for (int i = 0; i < 8; i++)
        #pragma unroll
        for (int j = 0; j < 8; j++) acc[i][j] = 0.f;

    const int arow_g = by*128 + a_row;
    for (int k0 = 0; k0 < K; k0 += 8) {
        float4 av = make_float4(0.f,0.f,0.f,0.f);
        if (arow_g < M)
            av = *(const float4*)(A + (size_t)arow_g*K + k0 + a_k);
        As[a_k+0][a_row] = av.x;
        As[a_k+1][a_row] = av.y;
        As[a_k+2][a_row] = av.z;
        As[a_k+3][a_row] = av.w;
        float4 bv = *(const float4*)(B + (size_t)(k0 + b_k)*Nc + bx*128 + b_col);
        *(float4*)&Bs[b_k][b_col] = bv;
        __syncthreads();

        #pragma unroll
        for (int k = 0; k < 8; k++) {
            float ar[8], br[8];
            *(float4*)&ar[0] = *(const float4*)&As[k][ty*8];
            *(float4*)&ar[4] = *(const float4*)&As[k][ty*8+4];
            *(float4*)&br[0] = *(const float4*)&Bs[k][tx*8];
            *(float4*)&br[4] = *(const float4*)&Bs[k][tx*8+4];
            #pragma unroll
            for (int i = 0; i < 8; i++)
                #pragma unroll
                for (int j = 0; j < 8; j++)
                    acc[i][j] += ar[i] * br[j];
        }
        __syncthreads();
    }

    #pragma unroll
    for (int i = 0; i < 8; i++) {
        int r = row0 + i;
        if (r >= M) break;
        #pragma unroll
        for (int j = 0; j < 8; j += 4) {
            float4 v = make_float4(acc[i][j], acc[i][j+1], acc[i][j+2], acc[i][j+3]);
            if (bias) {
                v.x += bias[col0+j+0]; v.y += bias[col0+j+1];
                v.z += bias[col0+j+2]; v.w += bias[col0+j+3];
            }
            if (doRelu) {
                v.x = fmaxf(v.x, 0.f); v.y = fmaxf(v.y, 0.f);
                v.z = fmaxf(v.z, 0.f); v.w = fmaxf(v.w, 0.f);
            }
            *(float4*)(C + (size_t)r*Nc + col0 + j) = v;
        }
    }
}

// ---------------- tiny head projection (t row stride HCAT) ----------------
__global__ void head2_k(const float* __restrict__ t, const float* __restrict__ Wf,
                        const float* __restrict__ bf, float* __restrict__ out, int od)
{
    int warp = (blockIdx.x*blockDim.x + threadIdx.x) >> 5;
    int lane = threadIdx.x & 31;
    if (warp >= NN) return;
    const float* tp = t + (size_t)warp*HCAT;
    float a0 = 0.f, a1 = 0.f;
    #pragma unroll 4
    for (int c = lane; c < FC; c += 32) {
        float v = tp[c];
        a0 += v * Wf[c*od + 0];
        if (od > 1) a1 += v * Wf[c*od + 1];
    }
    #pragma unroll
    for (int o = 16; o; o >>= 1) {
        a0 += __shfl_down_sync(0xffffffffu, a0, o);
        a1 += __shfl_down_sync(0xffffffffu, a1, o);
    }
    if (lane == 0) {
        out[(size_t)warp*od + 0] = a0 + bf[0];
        if (od > 1) out[(size_t)warp*od + 1] = a1 + bf[1];
    }
}

// ---------------- launch ----------------
extern "C" void kernel_launch(void* const* d_in, const int* in_sizes, int n_in,
                              void* d_out, int out_size)
{
    const float* z      = (const float*)d_in[0];
    const float* cond   = (const float*)d_in[1];
    const int*   ei     = (const int*)  d_in[2];
    const float* W_init = (const float*)d_in[4];
    const float* b_init = (const float*)d_in[5];
    const float* W1  = (const float*)d_in[6];
    const float* as1 = (const float*)d_in[7];
    const float* ad1 = (const float*)d_in[8];
    const float* b1  = (const float*)d_in[9];
    const float* W2  = (const float*)d_in[10];
    const float* as2 = (const float*)d_in[11];
    const float* ad2 = (const float*)d_in[12];
    const float* b2  = (const float*)d_in[13];
    const float* W3  = (const float*)d_in[14];
    const float* as3 = (const float*)d_in[15];
    const float* ad3 = (const float*)d_in[16];
    const float* b3  = (const float*)d_in[17];
    const float* Wp  = (const float*)d_in[18];
    const float* bp  = (const float*)d_in[19];
    const float* Wfp = (const float*)d_in[20];
    const float* bfp = (const float*)d_in[21];
    const float* Ws  = (const float*)d_in[22];
    const float* bs  = (const float*)d_in[23];
    const float* Wfs = (const float*)d_in[24];
    const float* bfs = (const float*)d_in[25];
    const float* Wt  = (const float*)d_in[26];
    const float* bt  = (const float*)d_in[27];
    const float* Wft = (const float*)d_in[28];
    const float* bft = (const float*)d_in[29];
    float* out = (float*)d_out;

    const int* esrc = ei;
    const int* edst = ei + NE;

    float *pxin, *pzc, *pY, *ph, *px, *pas, *pad, *pt, *phi, *plo, *pbc;
    float *pYS, *pYD, *pWS, *pWD;
    int *pcnt, *prow, *pwp, *pcol;
    cudaGetSymbolAddress((void**)&pxin, g_xin);
    cudaGetSymbolAddress((void**)&pzc,  g_zc);
    cudaGetSymbolAddress((void**)&pY,   g_Y);
    cudaGetSymbolAddress((void**)&ph,   g_h);
    cudaGetSymbolAddress((void**)&px,   g_x);
    cudaGetSymbolAddress((void**)&pas,  g_as);
    cudaGetSymbolAddress((void**)&pad,  g_ad);
    cudaGetSymbolAddress((void**)&pYS,  g_YS);
    cudaGetSymbolAddress((void**)&pYD,  g_YD);
    cudaGetSymbolAddress((void**)&pWS,  g_WS);
    cudaGetSymbolAddress((void**)&pWD,  g_WD);
    cudaGetSymbolAddress((void**)&pt,   g_t);
    cudaGetSymbolAddress((void**)&phi,  g_Bhi);
    cudaGetSymbolAddress((void**)&plo,  g_Blo);
    cudaGetSymbolAddress((void**)&pbc,  g_bcat);
    cudaGetSymbolAddress((void**)&pcnt, g_cnt);
    cudaGetSymbolAddress((void**)&prow, g_rowptr);
    cudaGetSymbolAddress((void**)&pwp,  g_wp);
    cudaGetSymbolAddress((void**)&pcol, g_col);

    cudaFuncSetAttribute(mgemm_k, cudaFuncAttributeMaxDynamicSharedMemorySize, SMEM_MG);

    // 1) input projection (small, SIMT fp32)
    concat_k<<<(NB*KIN + 255)/256, 256>>>(z, cond, pxin);
    {
        dim3 g(LAT/128, 1);
        sgemm_k<<<g, 256>>>(pxin, W_init, b_init, pzc, NB, LAT, KIN, 1);
    }
    {
        dim3 g(HF/128, 1);
        sgemm_k<<<g, 256>>>(pzc, W1, nullptr, pY, NB, HF, LAT, 0);
    }
    // 2) CSR by destination
    zero_cnt_k<<<(NN + 255)/256, 256>>>(pcnt);
    count_k<<<(NE + 255)/256, 256>>>(edst, pcnt);
    scan_k<<<1, 256>>>(pcnt, prow, pwp);
    scatter_k<<<(NE + 255)/256, 256>>>(esrc, edst, pwp, pcol);

    // 3) h1 = Y[batch] + W1[256+order]
    build_h1_k<<<(NN*(HF/4) + 255)/256, 256>>>(pY, W1, ph);

    // 4) layer 1: att via exact decomposition (h1 = Y[b] + W1[256+o])
    dotrow_k<<<(NB*NH*32 + 255)/256, 256>>>(pY, as1, ad1, pYS, pYD, NB);
    dotrow_k<<<(NPG*NH*32 + 255)/256, 256>>>(W1 + (size_t)LAT*HF, as1, ad1, pWS, pWD, NPG);
    attcomb_k<<<(NN*NH + 255)/256, 256>>>(pYS, pYD, pWS, pWD, pas, pad);
    agg_k<<<NN, 256>>>(ph, pas, pad, prow, pcol, b1, px);

    // 5) layer 2: GEMM with fused att2 reduction
    zero2_k<<<(NN*NH + 255)/256, 256>>>(pas, pad);
    wsplit_k<<<(HF*HF + 255)/256, 256>>>(W2, phi, plo, HF*HF);
    mgemm_k<<<dim3(HF/128, NN/128), 256, SMEM_MG>>>(px, phi, plo, ph, HF, nullptr, 0,
                                                    as2, ad2, pas, pad);
    agg_k<<<NN, 256>>>(ph, pas, pad, prow, pcol, b2, px);

    // 6) layer 3
    zero2_k<<<(NN*NH + 255)/256, 256>>>(pas, pad);
    wsplit_k<<<(HF*HF + 255)/256, 256>>>(W3, phi, plo, HF*HF);
    mgemm_k<<<dim3(HF/128, NN/128), 256, SMEM_MG>>>(px, phi, plo, ph, HF, nullptr, 0,
                                                    as3, ad3, pas, pad);
    agg_k<<<NN, 256>>>(ph, pas, pad, prow, pcol, b3, px);

    // 7) heads: merged t = relu(x @ [Wp|Ws|Wt] + bcat) in ONE Nc=768 GEMM
    hcat_k<<<(HF*HCAT + 255)/256, 256>>>(Wp, Ws, Wt, bp, bs, bt, phi, plo, pbc);
    mgemm_k<<<dim3(HCAT/128, NN/128), 256, SMEM_MG>>>(px, phi, plo, pt, HCAT, pbc, 1,
                                                      nullptr, nullptr, nullptr, nullptr);

    head2_k<<<(NN*32 + 255)/256, 256>>>(pt,       Wfp, bfp, out, 2);
    head2_k<<<(NN*32 + 255)/256, 256>>>(pt + 256, Wfs, bfs, out + (size_t)2*NN, 2);
    head2_k<<<(NN*32 + 255)/256, 256>>>(pt + 512, Wft, bft, out + (size_t)4*NN, 1);
}